// round 7
// baseline (speedup 1.0000x reference)
#include <cuda_runtime.h>
#include <cuda_bf16.h>
#include <math.h>

// Problem constants
#define BB 256   // batch
#define SS 512   // seq len
#define HH 1024  // hidden
#define EE 256   // input dim
#define CC 128   // num classes

typedef unsigned long long u64;

// ---------------- device scratch (no allocations allowed) ----------------
__device__ float  g_Gf[CC * HH];         // emb@Wfx^T + bf
__device__ float  g_Gi[CC * HH];         // emb@Wix^T + bi
__device__ float  g_Go[CC * HH];         // emb@Wox^T + bo
__device__ float  g_Sc[CC * HH];         // sigmoid(emb@Wcx^T + bc)
__device__ u64    g_cd[2][HH * BB];      // cell state, transposed + DUPLICATED: [buf][k*BB + b] = {c,c}
__device__ float2 g_Wfi[HH * HH];        // [k][n] = {wf, wi}   (8MB)
__device__ u64    g_WoD[HH * HH];        // [k][n] = {wo, wo}   (8MB)
__device__ float  g_h[BB * HH];          // final hidden [b][h]
__device__ unsigned g_bar[4];            // per-m-group barrier counters

// ---------------- helpers ----------------
__device__ __forceinline__ float sigmoidf_(float x) {
    return 1.0f / (1.0f + __expf(-x));
}
__device__ __forceinline__ u64 pk2b(float v) {
    u64 r; asm("mov.b64 %0, {%1, %1};" : "=l"(r) : "f"(v)); return r;
}
__device__ __forceinline__ void upk2(u64 v, float& lo, float& hi) {
    asm("mov.b64 {%0, %1}, %2;" : "=f"(lo), "=f"(hi) : "l"(v));
}
__device__ __forceinline__ u64 fma2(u64 a, u64 b, u64 c) {
    u64 d; asm("fma.rn.f32x2 %0, %1, %2, %3;" : "=l"(d) : "l"(a), "l"(b), "l"(c)); return d;
}
__device__ __forceinline__ unsigned int smem_u32(const void* p) {
    return (unsigned int)__cvta_generic_to_shared(p);
}
__device__ __forceinline__ void cpa16(void* dst, const void* src) {
    asm volatile("cp.async.cg.shared.global [%0], [%1], 16;\n"
                 :: "r"(smem_u32(dst)), "l"(src));
}
#define CP_COMMIT() asm volatile("cp.async.commit_group;\n" ::: "memory")
#define CP_WAIT0()  asm volatile("cp.async.wait_group 0;\n" ::: "memory")

// per-m-group grid barrier (32 co-resident blocks per group, monotonic counter)
__device__ __forceinline__ void mg_barrier(int mg, unsigned goal) {
    __syncthreads();
    if (threadIdx.x == 0) {
        __threadfence();
        atomicAdd(&g_bar[mg], 1u);
        unsigned v;
        do {
            asm volatile("ld.acquire.gpu.global.u32 %0, [%1];"
                         : "=r"(v) : "l"(g_bar + mg) : "memory");
        } while (v < goal);
    }
    __syncthreads();
}

// ---------------- kernel: zero initial cell state + barrier counters ----------------
// Zeroes EXACTLY g_cd[0] (the t=0 input buffer). g_cd[1] is written before read.
#define C0_FLOAT4 ((int)(sizeof(g_cd[0]) / sizeof(float4)))   // 131072
__global__ void zero_kernel() {
    int i = blockIdx.x * blockDim.x + threadIdx.x;
    if (i < C0_FLOAT4)
        reinterpret_cast<float4*>(g_cd[0])[i] = make_float4(0.f, 0.f, 0.f, 0.f);
    if (blockIdx.x == 0 && threadIdx.x < 4) g_bar[threadIdx.x] = 0u;
}

// ---------------- kernel: transpose + gate-pack Wfh/Wih -> float2{wf,wi} ----------------
__global__ __launch_bounds__(256)
void transpose_fi_kernel(const float* __restrict__ Wf, const float* __restrict__ Wi) {
    __shared__ float tf[32][33], ti[32][33];
    const int k0 = blockIdx.x * 32;
    const int n0 = blockIdx.y * 32;
    const int tx = threadIdx.x & 31;
    const int ty = threadIdx.x >> 5;
#pragma unroll
    for (int r = 0; r < 4; r++) {
        const int row = ty + r * 8;
        tf[row][tx] = Wf[(size_t)(n0 + row) * HH + k0 + tx];
        ti[row][tx] = Wi[(size_t)(n0 + row) * HH + k0 + tx];
    }
    __syncthreads();
#pragma unroll
    for (int r = 0; r < 4; r++) {
        const int row = ty + r * 8;     // output k = k0+row, n = n0+tx
        g_Wfi[(size_t)(k0 + row) * HH + n0 + tx] = make_float2(tf[tx][row], ti[tx][row]);
    }
}

// ---------------- kernel: transpose + duplicate-pack Woh ----------------
__global__ __launch_bounds__(256)
void transpose_o_kernel(const float* __restrict__ Wo) {
    __shared__ float t[32][33];
    const int k0 = blockIdx.x * 32;
    const int n0 = blockIdx.y * 32;
    const int tx = threadIdx.x & 31;
    const int ty = threadIdx.x >> 5;
#pragma unroll
    for (int r = 0; r < 4; r++) {
        const int row = ty + r * 8;
        t[row][tx] = Wo[(size_t)(n0 + row) * HH + k0 + tx];
    }
    __syncthreads();
#pragma unroll
    for (int r = 0; r < 4; r++) {
        const int row = ty + r * 8;
        g_WoD[(size_t)(k0 + row) * HH + n0 + tx] = pk2b(t[tx][row]);
    }
}

// ---------------- kernel: precompute class->gate tables ----------------
__global__ __launch_bounds__(256)
void tab_kernel(const float* __restrict__ emb,
                const float* __restrict__ Wfx, const float* __restrict__ Wix,
                const float* __restrict__ Wox, const float* __restrict__ Wcx,
                const float* __restrict__ bf,  const float* __restrict__ bi,
                const float* __restrict__ bo,  const float* __restrict__ bc) {
    __shared__ float es[32][33];
    __shared__ float ws[4][32][33];

    const int tid = threadIdx.x;
    const int h0  = blockIdx.x * 32;
    const int c0b = blockIdx.y * 32;
    const int tx  = tid & 31;
    const int ty  = tid >> 5;

    float acc[4][4];
#pragma unroll
    for (int m = 0; m < 4; m++)
#pragma unroll
        for (int q = 0; q < 4; q++) acc[m][q] = 0.f;

    for (int k0 = 0; k0 < EE; k0 += 32) {
        __syncthreads();
        const int ccol  = tid & 31;
        const int rbase = tid >> 5;
#pragma unroll
        for (int rr = 0; rr < 4; rr++) {
            const int r = rbase + rr * 8;
            es[r][ccol]    = emb[(c0b + r) * EE + k0 + ccol];
            ws[0][r][ccol] = Wfx[(h0 + r) * EE + k0 + ccol];
            ws[1][r][ccol] = Wix[(h0 + r) * EE + k0 + ccol];
            ws[2][r][ccol] = Wox[(h0 + r) * EE + k0 + ccol];
            ws[3][r][ccol] = Wcx[(h0 + r) * EE + k0 + ccol];
        }
        __syncthreads();
#pragma unroll
        for (int kk = 0; kk < 32; kk++) {
            const float b0 = ws[0][tx][kk];
            const float b1 = ws[1][tx][kk];
            const float b2 = ws[2][tx][kk];
            const float b3 = ws[3][tx][kk];
#pragma unroll
            for (int q = 0; q < 4; q++) {
                const float a = es[ty + q * 8][kk];
                acc[0][q] = fmaf(a, b0, acc[0][q]);
                acc[1][q] = fmaf(a, b1, acc[1][q]);
                acc[2][q] = fmaf(a, b2, acc[2][q]);
                acc[3][q] = fmaf(a, b3, acc[3][q]);
            }
        }
    }

    const int h = h0 + tx;
    const float vbf = bf[h], vbi = bi[h], vbo = bo[h], vbc = bc[h];
#pragma unroll
    for (int q = 0; q < 4; q++) {
        const int cls = c0b + ty + q * 8;
        g_Gf[cls * HH + h] = acc[0][q] + vbf;
        g_Gi[cls * HH + h] = acc[1][q] + vbi;
        g_Go[cls * HH + h] = acc[2][q] + vbo;
        g_Sc[cls * HH + h] = sigmoidf_(acc[3][q] + vbc);
    }
}

// ---------------- persistent kernel: all 512 steps + final o-gate ----------------
// Tile M=64 (batch), N=32 (hidden). grid (32 n-tiles, 4 m-groups), 256 threads.
// Dynamic smem: ad_s u64[2][32][64] (32KB) | wfi_s u64[2][32][32] (16KB) = 48KB
// Accumulator pairing: acc[j] = {acc_f, acc_i} for batch j; W operand = {wf,wi};
// A operand = {c,c} (duplicated in gmem, broadcast across lanes in smem).
__global__ __launch_bounds__(256, 1)
void persist_kernel(const int* __restrict__ x) {
    extern __shared__ __align__(16) char dynsm[];
    u64    (*ad_s)[32][64]  = reinterpret_cast<u64(*)[32][64]>(dynsm);
    u64    (*wfi_s)[32][32] = reinterpret_cast<u64(*)[32][32]>(dynsm + 32768);
    u64    (*wo_s)[32][32]  = reinterpret_cast<u64(*)[32][32]>(dynsm + 32768);
    __shared__ int cls_s[64];

    const int tid = threadIdx.x;
    const int mg  = blockIdx.y;        // m-group 0..3
    const int M0  = mg * 64;
    const int N0  = blockIdx.x * 32;

    const int tx  = tid & 31;          // n lane
    const int ty  = tid >> 5;          // warp id; owns block-local batches [ty*8, ty*8+8)
    const int lb0 = ty * 8;

    const int prow = tid >> 3;         // 0..31 (k row within tile)
    const int pcol = tid & 7;          // 0..7

    const float2* wS = g_Wfi + (size_t)prow * HH + N0 + pcol * 4;

    // prefetch W tile 0 (constant across steps)
#pragma unroll
    for (int j = 0; j < 2; j++) cpa16(&wfi_s[0][prow][pcol * 4 + 2 * j],
                                      reinterpret_cast<const char*>(wS) + 16 * j);
    CP_COMMIT();

#pragma unroll 1
    for (int t = 0; t < SS; t++) {
        const u64* __restrict__ cin  = g_cd[t & 1];
        u64*       __restrict__ cout = g_cd[(t & 1) ^ 1];
        if (tid < 64) cls_s[tid] = x[(M0 + tid) * SS + t];

        const u64* aS = cin + (size_t)prow * BB + M0 + pcol * 8;
        // prefetch A tile 0
#pragma unroll
        for (int j = 0; j < 4; j++) cpa16(&ad_s[0][prow][pcol * 8 + 2 * j], aS + 2 * j);
        CP_COMMIT();

        u64 acc[8];
#pragma unroll
        for (int p = 0; p < 8; p++) acc[p] = 0ull;

#pragma unroll 1
        for (int it = 0; it < 32; it++) {
            const int buf = it & 1;
            CP_WAIT0();
            __syncthreads();
            if (it < 31) {
                const size_t aoff = (size_t)(it + 1) * 32 * BB;   // u64 units
                const size_t woff = (size_t)(it + 1) * 32 * HH;   // float2 units
#pragma unroll
                for (int j = 0; j < 4; j++)
                    cpa16(&ad_s[buf ^ 1][prow][pcol * 8 + 2 * j], aS + aoff + 2 * j);
#pragma unroll
                for (int j = 0; j < 2; j++)
                    cpa16(&wfi_s[buf ^ 1][prow][pcol * 4 + 2 * j],
                          reinterpret_cast<const char*>(wS + woff) + 16 * j);
                CP_COMMIT();
            }
#pragma unroll
            for (int kk = 0; kk < 32; kk++) {
                const u64 w = wfi_s[buf][kk][tx];                  // {wf, wi}
                const ulonglong2 A01 = *reinterpret_cast<const ulonglong2*>(&ad_s[buf][kk][lb0]);
                const ulonglong2 A23 = *reinterpret_cast<const ulonglong2*>(&ad_s[buf][kk][lb0 + 2]);
                const ulonglong2 A45 = *reinterpret_cast<const ulonglong2*>(&ad_s[buf][kk][lb0 + 4]);
                const ulonglong2 A67 = *reinterpret_cast<const ulonglong2*>(&ad_s[buf][kk][lb0 + 6]);
                acc[0] = fma2(A01.x, w, acc[0]);
                acc[1] = fma2(A01.y, w, acc[1]);
                acc[2] = fma2(A23.x, w, acc[2]);
                acc[3] = fma2(A23.y, w, acc[3]);
                acc[4] = fma2(A45.x, w, acc[4]);
                acc[5] = fma2(A45.y, w, acc[5]);
                acc[6] = fma2(A67.x, w, acc[6]);
                acc[7] = fma2(A67.y, w, acc[7]);
            }
        }

        // epilogue: gates + cell update (8 batches per thread, fixed n)
        const int n = N0 + tx;
#pragma unroll
        for (int p = 0; p < 8; p += 2) {
            const int b0 = M0 + lb0 + p;
            // old c (dup format; take lo half)
            const ulonglong2 cd = *reinterpret_cast<const ulonglong2*>(&cin[(size_t)n * BB + b0]);
            float c0o, dmy0, c1o, dmy1;
            upk2(cd.x, c0o, dmy0);
            upk2(cd.y, c1o, dmy1);
            float af0, ai0, af1, ai1;
            upk2(acc[p],     af0, ai0);
            upk2(acc[p + 1], af1, ai1);
            const int cls0 = cls_s[lb0 + p];
            const int cls1 = cls_s[lb0 + p + 1];
            const float f0 = sigmoidf_(af0 + __ldg(&g_Gf[cls0 * HH + n]));
            const float i0 = sigmoidf_(ai0 + __ldg(&g_Gi[cls0 * HH + n]));
            const float f1 = sigmoidf_(af1 + __ldg(&g_Gf[cls1 * HH + n]));
            const float i1 = sigmoidf_(ai1 + __ldg(&g_Gi[cls1 * HH + n]));
            const float cn0 = __ldg(&g_Sc[cls0 * HH + n]) * i0 + c0o * f0;
            const float cn1 = __ldg(&g_Sc[cls1 * HH + n]) * i1 + c1o * f1;
            ulonglong2 o2;
            o2.x = pk2b(cn0);
            o2.y = pk2b(cn1);
            *reinterpret_cast<ulonglong2*>(&cout[(size_t)n * BB + b0]) = o2;
        }

        if (t < SS - 1) {
            // prefetch W tile 0 for next step (constant data, safe pre-barrier)
#pragma unroll
            for (int j = 0; j < 2; j++) cpa16(&wfi_s[0][prow][pcol * 4 + 2 * j],
                                              reinterpret_cast<const char*>(wS) + 16 * j);
            CP_COMMIT();
        }
        mg_barrier(mg, (unsigned)(t + 1) * 32u);
    }

    // ---- final o-gate phase: o from c_prev (g_cd[1]), h = tanh(c_last)*o ----
    {
        const u64* __restrict__ cprev = g_cd[1];
        const u64* __restrict__ clast = g_cd[0];
        const u64* aS  = cprev + (size_t)prow * BB + M0 + pcol * 8;
        const u64* woS = g_WoD + (size_t)prow * HH + N0 + pcol * 4;

        // prefetch tile 0 (A + Wo)
#pragma unroll
        for (int j = 0; j < 4; j++) cpa16(&ad_s[0][prow][pcol * 8 + 2 * j], aS + 2 * j);
#pragma unroll
        for (int j = 0; j < 2; j++) cpa16(&wo_s[0][prow][pcol * 4 + 2 * j], woS + 2 * j);
        CP_COMMIT();

        u64 acc[8];
#pragma unroll
        for (int p = 0; p < 8; p++) acc[p] = 0ull;

#pragma unroll 1
        for (int it = 0; it < 32; it++) {
            const int buf = it & 1;
            CP_WAIT0();
            __syncthreads();
            if (it < 31) {
                const size_t aoff = (size_t)(it + 1) * 32 * BB;
                const size_t woff = (size_t)(it + 1) * 32 * HH;
#pragma unroll
                for (int j = 0; j < 4; j++)
                    cpa16(&ad_s[buf ^ 1][prow][pcol * 8 + 2 * j], aS + aoff + 2 * j);
#pragma unroll
                for (int j = 0; j < 2; j++)
                    cpa16(&wo_s[buf ^ 1][prow][pcol * 4 + 2 * j], woS + woff + 2 * j);
                CP_COMMIT();
            }
#pragma unroll
            for (int kk = 0; kk < 32; kk++) {
                const u64 w = wo_s[buf][kk][tx];                  // {wo, wo}
                const ulonglong2 A01 = *reinterpret_cast<const ulonglong2*>(&ad_s[buf][kk][lb0]);
                const ulonglong2 A23 = *reinterpret_cast<const ulonglong2*>(&ad_s[buf][kk][lb0 + 2]);
                const ulonglong2 A45 = *reinterpret_cast<const ulonglong2*>(&ad_s[buf][kk][lb0 + 4]);
                const ulonglong2 A67 = *reinterpret_cast<const ulonglong2*>(&ad_s[buf][kk][lb0 + 6]);
                acc[0] = fma2(A01.x, w, acc[0]);
                acc[1] = fma2(A01.y, w, acc[1]);
                acc[2] = fma2(A23.x, w, acc[2]);
                acc[3] = fma2(A23.y, w, acc[3]);
                acc[4] = fma2(A45.x, w, acc[4]);
                acc[5] = fma2(A45.y, w, acc[5]);
                acc[6] = fma2(A67.x, w, acc[6]);
                acc[7] = fma2(A67.y, w, acc[7]);
            }
        }

        const int n = N0 + tx;
#pragma unroll
        for (int p = 0; p < 8; p++) {
            const int lb = lb0 + p;
            const int b  = M0 + lb;
            float ao, dmy;
            upk2(acc[p], ao, dmy);
            float cl, dmy2;
            upk2(clast[(size_t)n * BB + b], cl, dmy2);
            const int cls = cls_s[lb];   // still holds t=511 classes
            const float o = sigmoidf_(ao + __ldg(&g_Go[cls * HH + n]));
            g_h[(size_t)b * HH + n] = tanhf(cl) * o;
        }
    }
}

// ---------------- kernel: logits + log_softmax ----------------
__global__ __launch_bounds__(128)
void logits_kernel(const float* __restrict__ Wph, const float* __restrict__ bp,
                   float* __restrict__ out) {
    const int b = blockIdx.x;
    const int j = threadIdx.x;

    __shared__ __align__(16) float h_s[HH];
    __shared__ float red[128];

    const float4* hv  = reinterpret_cast<const float4*>(&g_h[(size_t)b * HH]);
    float4*       hs4 = reinterpret_cast<float4*>(h_s);
    for (int i = j; i < HH / 4; i += 128) hs4[i] = hv[i];
    __syncthreads();

    float acc = 0.f;
    const float4* w4 = reinterpret_cast<const float4*>(&Wph[(size_t)j * HH]);
#pragma unroll 4
    for (int k = 0; k < HH / 4; k++) {
        const float4 w = w4[k];
        const float4 h = hs4[k];
        acc = fmaf(h.x, w.x, acc);
        acc = fmaf(h.y, w.y, acc);
        acc = fmaf(h.z, w.z, acc);
        acc = fmaf(h.w, w.w, acc);
    }
    const float p = acc + bp[j];

    red[j] = p;
    __syncthreads();
    for (int s2 = 64; s2 > 0; s2 >>= 1) {
        if (j < s2) red[j] = fmaxf(red[j], red[j + s2]);
        __syncthreads();
    }
    const float mx = red[0];
    __syncthreads();
    red[j] = expf(p - mx);
    __syncthreads();
    for (int s2 = 64; s2 > 0; s2 >>= 1) {
        if (j < s2) red[j] += red[j + s2];
        __syncthreads();
    }
    const float lse = logf(red[0]) + mx;
    out[b * CC + j] = p - lse;
}

// ---------------- launcher ----------------
extern "C" void kernel_launch(void* const* d_in, const int* in_sizes, int n_in,
                              void* d_out, int out_size) {
    const int*   x   = (const int*)  d_in[0];
    const float* emb = (const float*)d_in[1];
    const float* Wcx = (const float*)d_in[2];
    const float* bc  = (const float*)d_in[3];
    const float* Wix = (const float*)d_in[4];
    const float* Wih = (const float*)d_in[5];
    const float* bi  = (const float*)d_in[6];
    const float* Wfx = (const float*)d_in[7];
    const float* Wfh = (const float*)d_in[8];
    const float* bf  = (const float*)d_in[9];
    const float* Wox = (const float*)d_in[10];
    const float* Woh = (const float*)d_in[11];
    const float* bo  = (const float*)d_in[12];
    const float* Wph = (const float*)d_in[13];
    const float* bp  = (const float*)d_in[14];
    float* out = (float*)d_out;

    const int dyn_smem = 32768 + 16384;  // A-dup (32KB) + W (16KB)
    cudaFuncSetAttribute(persist_kernel,
                         cudaFuncAttributeMaxDynamicSharedMemorySize, dyn_smem);

    transpose_fi_kernel<<<dim3(32, 32), 256>>>(Wfh, Wih);
    transpose_o_kernel<<<dim3(32, 32), 256>>>(Woh);
    tab_kernel<<<dim3(32, 4), 256>>>(emb, Wfx, Wix, Wox, Wcx, bf, bi, bo, bc);

    const int zgrid = (C0_FLOAT4 + 255) / 256;   // exactly covers g_cd[0]
    zero_kernel<<<zgrid, 256>>>();

    persist_kernel<<<dim3(32, 4), 256, dyn_smem>>>(x);

    logits_kernel<<<BB, 128>>>(Wph, bp, out);
}

// round 8
// speedup vs baseline: 1.6340x; 1.6340x over previous
#include <cuda_runtime.h>
#include <cuda_bf16.h>
#include <math.h>

// Problem constants
#define BB 256   // batch
#define SS 512   // seq len
#define HH 1024  // hidden
#define EE 256   // input dim
#define CC 128   // num classes

typedef unsigned long long u64;

// ---------------- device scratch (no allocations allowed) ----------------
__device__ float g_Gf[CC * HH];          // emb@Wfx^T + bf
__device__ float g_Gi[CC * HH];          // emb@Wix^T + bi
__device__ float g_Go[CC * HH];          // emb@Wox^T + bo
__device__ float g_Sc[CC * HH];          // sigmoid(emb@Wcx^T + bc)
__device__ u64   g_c2[2][HH * (BB/2)];   // cell state, transposed+paired: [buf][k*128 + bpair]
__device__ float g_WfT[HH * HH];         // Wfh transposed -> [k][n]
__device__ float g_WiT[HH * HH];
__device__ float g_WoT[HH * HH];
__device__ float g_h [BB * HH];          // final hidden (row-major [b][h])

// ---------------- helpers ----------------
__device__ __forceinline__ float sigmoidf_(float x) {
    return 1.0f / (1.0f + __expf(-x));
}
__device__ __forceinline__ u64 pk2(float lo, float hi) {
    u64 r; asm("mov.b64 %0, {%1, %2};" : "=l"(r) : "f"(lo), "f"(hi)); return r;
}
__device__ __forceinline__ u64 pk2b(float v) {
    u64 r; asm("mov.b64 %0, {%1, %1};" : "=l"(r) : "f"(v)); return r;
}
__device__ __forceinline__ void upk2(u64 v, float& lo, float& hi) {
    asm("mov.b64 {%0, %1}, %2;" : "=f"(lo), "=f"(hi) : "l"(v));
}
__device__ __forceinline__ u64 fma2(u64 a, u64 b, u64 c) {
    u64 d; asm("fma.rn.f32x2 %0, %1, %2, %3;" : "=l"(d) : "l"(a), "l"(b), "l"(c)); return d;
}
__device__ __forceinline__ unsigned int smem_u32(const void* p) {
    return (unsigned int)__cvta_generic_to_shared(p);
}
__device__ __forceinline__ void cpa16(void* dst, const void* src) {
    asm volatile("cp.async.cg.shared.global [%0], [%1], 16;\n"
                 :: "r"(smem_u32(dst)), "l"(src));
}
#define CP_COMMIT() asm volatile("cp.async.commit_group;\n" ::: "memory")
#define CP_WAIT0()  asm volatile("cp.async.wait_group 0;\n" ::: "memory")

// ---------------- kernel: zero the initial cell state (exactly g_c2[0]) ----------------
#define C0_FLOAT4 ((int)(sizeof(g_c2[0]) / sizeof(float4)))
__global__ void zero_kernel() {
    int i = blockIdx.x * blockDim.x + threadIdx.x;
    if (i < C0_FLOAT4)
        reinterpret_cast<float4*>(g_c2[0])[i] = make_float4(0.f, 0.f, 0.f, 0.f);
}

// ---------------- kernel: 32x32 tiled transpose [n][k] -> [k][n] ----------------
__global__ __launch_bounds__(256)
void transpose_kernel(const float* __restrict__ in, float* __restrict__ out) {
    __shared__ float t[32][33];
    const int k0 = blockIdx.x * 32;
    const int n0 = blockIdx.y * 32;
    const int tx = threadIdx.x & 31;
    const int ty = threadIdx.x >> 5;   // 0..7
#pragma unroll
    for (int r = 0; r < 4; r++) {
        const int row = ty + r * 8;
        t[row][tx] = in[(size_t)(n0 + row) * HH + k0 + tx];
    }
    __syncthreads();
#pragma unroll
    for (int r = 0; r < 4; r++) {
        const int row = ty + r * 8;
        out[(size_t)(k0 + row) * HH + n0 + tx] = t[tx][row];
    }
}

// ---------------- kernel: precompute class->gate tables ----------------
// M=128 (cls), N=1024 (h), K=256.  grid: (32 h-tiles, 4 cls-tiles), 256 threads.
__global__ __launch_bounds__(256)
void tab_kernel(const float* __restrict__ emb,
                const float* __restrict__ Wfx, const float* __restrict__ Wix,
                const float* __restrict__ Wox, const float* __restrict__ Wcx,
                const float* __restrict__ bf,  const float* __restrict__ bi,
                const float* __restrict__ bo,  const float* __restrict__ bc) {
    __shared__ float es[32][33];      // [cls][k]
    __shared__ float ws[4][32][33];   // [table][h][k]

    const int tid = threadIdx.x;
    const int h0  = blockIdx.x * 32;
    const int c0b = blockIdx.y * 32;
    const int tx  = tid & 31;
    const int ty  = tid >> 5;

    float acc[4][4];
#pragma unroll
    for (int m = 0; m < 4; m++)
#pragma unroll
        for (int q = 0; q < 4; q++) acc[m][q] = 0.f;

    for (int k0 = 0; k0 < EE; k0 += 32) {
        __syncthreads();
        const int ccol  = tid & 31;
        const int rbase = tid >> 5;
#pragma unroll
        for (int rr = 0; rr < 4; rr++) {
            const int r = rbase + rr * 8;
            es[r][ccol]    = emb[(c0b + r) * EE + k0 + ccol];
            ws[0][r][ccol] = Wfx[(h0 + r) * EE + k0 + ccol];
            ws[1][r][ccol] = Wix[(h0 + r) * EE + k0 + ccol];
            ws[2][r][ccol] = Wox[(h0 + r) * EE + k0 + ccol];
            ws[3][r][ccol] = Wcx[(h0 + r) * EE + k0 + ccol];
        }
        __syncthreads();
#pragma unroll
        for (int kk = 0; kk < 32; kk++) {
            const float b0 = ws[0][tx][kk];
            const float b1 = ws[1][tx][kk];
            const float b2 = ws[2][tx][kk];
            const float b3 = ws[3][tx][kk];
#pragma unroll
            for (int q = 0; q < 4; q++) {
                const float a = es[ty + q * 8][kk];
                acc[0][q] = fmaf(a, b0, acc[0][q]);
                acc[1][q] = fmaf(a, b1, acc[1][q]);
                acc[2][q] = fmaf(a, b2, acc[2][q]);
                acc[3][q] = fmaf(a, b3, acc[3][q]);
            }
        }
    }

    const int h = h0 + tx;
    const float vbf = bf[h], vbi = bi[h], vbo = bo[h], vbc = bc[h];
#pragma unroll
    for (int q = 0; q < 4; q++) {
        const int cls = c0b + ty + q * 8;
        g_Gf[cls * HH + h] = acc[0][q] + vbf;
        g_Gi[cls * HH + h] = acc[1][q] + vbi;
        g_Go[cls * HH + h] = acc[2][q] + vbo;
        g_Sc[cls * HH + h] = sigmoidf_(acc[3][q] + vbc);
    }
}

// ---------------- kernel: one recurrence step ----------------
// c_out[b,n] = Sc[cls,n]*sig(Gi[cls,n]+c.Wih[n]) + c[b,n]*sig(Gf[cls,n]+c.Wfh[n])
// GEMM M=256(b) x N=1024(n) x K=1024. A (cell state) transposed+b-paired (u64),
// W transposed [k][n]. Tile M=64, N=32, K-tile=64, double-buffered cp.async.
// Epilogue table gathers hoisted to step start (latency hidden under GEMM).
// grid (32 n-tiles, 4 m-tiles), 256 threads. Dynamic smem 64KB:
//   a_s  u64  [2][64][32]  32KB @ 0
//   wf_s float[2][64][32]  16KB @ 32768
//   wi_s float[2][64][32]  16KB @ 49152
__global__ __launch_bounds__(256)
void step_kernel(const int* __restrict__ x, int t) {
    const u64* __restrict__ cin  = g_c2[t & 1];
    u64*       __restrict__ cout = g_c2[(t & 1) ^ 1];

    extern __shared__ __align__(16) char dynsm[];
    u64   (*a_s)[64][32]  = reinterpret_cast<u64(*)[64][32]>(dynsm);
    float (*wf_s)[64][32] = reinterpret_cast<float(*)[64][32]>(dynsm + 32768);
    float (*wi_s)[64][32] = reinterpret_cast<float(*)[64][32]>(dynsm + 49152);
    __shared__ int cls_s[64];

    const int tid = threadIdx.x;
    const int M0  = blockIdx.y * 64;   // batch offset
    const int N0  = blockIdx.x * 32;   // hidden offset
    if (tid < 64) cls_s[tid] = x[(M0 + tid) * SS + t];

    const int tx  = tid & 31;          // n lane
    const int ty  = tid >> 5;          // warp id -> bpair group
    const int mpb = ty * 4;            // block-local bpair base

    // cp.async thread map for K-tile 64:
    // A: 64 rows x 32 u64 -> 8 u64/thread (4x cpa16); W: 64 x 32 f -> 8 f/thread (2x)
    const int arow  = tid >> 2;        // 0..63
    const int acolb = (tid & 3) * 8;   // 0,8,16,24
    const u64*   aS = cin   + (size_t)arow * (BB/2) + (M0 >> 1) + acolb;
    const float* fS = g_WfT + (size_t)arow * HH + N0 + acolb;
    const float* iS = g_WiT + (size_t)arow * HH + N0 + acolb;

    // prefetch tile 0 into buf 0
#pragma unroll
    for (int j = 0; j < 4; j++) cpa16(&a_s[0][arow][acolb + 2 * j], aS + 2 * j);
#pragma unroll
    for (int j = 0; j < 2; j++) cpa16(&wf_s[0][arow][acolb + 4 * j], fS + 4 * j);
#pragma unroll
    for (int j = 0; j < 2; j++) cpa16(&wi_s[0][arow][acolb + 4 * j], iS + 4 * j);
    CP_COMMIT();

    __syncthreads();   // cls_s visible

    // ---- hoisted epilogue operands (latency hidden under the GEMM) ----
    const int n = N0 + tx;
    float hGf[8], hGi[8], hSc[8];
    u64   hCold[4];
#pragma unroll
    for (int p = 0; p < 4; p++) {
        const int lm   = 2 * (mpb + p);
        const int cls0 = cls_s[lm];
        const int cls1 = cls_s[lm + 1];
        hGf[2 * p]     = __ldg(&g_Gf[cls0 * HH + n]);
        hGf[2 * p + 1] = __ldg(&g_Gf[cls1 * HH + n]);
        hGi[2 * p]     = __ldg(&g_Gi[cls0 * HH + n]);
        hGi[2 * p + 1] = __ldg(&g_Gi[cls1 * HH + n]);
        hSc[2 * p]     = __ldg(&g_Sc[cls0 * HH + n]);
        hSc[2 * p + 1] = __ldg(&g_Sc[cls1 * HH + n]);
        hCold[p]       = __ldg(&cin[(size_t)n * (BB/2) + (M0 >> 1) + mpb + p]);
    }

    u64 accf[4], acci[4];
#pragma unroll
    for (int p = 0; p < 4; p++) { accf[p] = 0ull; acci[p] = 0ull; }

#pragma unroll 1
    for (int it = 0; it < 16; it++) {
        const int buf = it & 1;
        CP_WAIT0();
        __syncthreads();          // tile `it` resident

        if (it < 15) {            // prefetch tile it+1 into the other buffer
            const size_t aoff = (size_t)(it + 1) * 64 * (BB/2);
            const size_t woff = (size_t)(it + 1) * 64 * HH;
#pragma unroll
            for (int j = 0; j < 4; j++)
                cpa16(&a_s[buf ^ 1][arow][acolb + 2 * j], aS + aoff + 2 * j);
#pragma unroll
            for (int j = 0; j < 2; j++)
                cpa16(&wf_s[buf ^ 1][arow][acolb + 4 * j], fS + woff + 4 * j);
#pragma unroll
            for (int j = 0; j < 2; j++)
                cpa16(&wi_s[buf ^ 1][arow][acolb + 4 * j], iS + woff + 4 * j);
            CP_COMMIT();
        }

#pragma unroll
        for (int kk = 0; kk < 64; kk++) {
            const u64 wf2 = pk2b(wf_s[buf][kk][tx]);
            const u64 wi2 = pk2b(wi_s[buf][kk][tx]);
            const ulonglong2 A01 = *reinterpret_cast<const ulonglong2*>(&a_s[buf][kk][mpb]);
            const ulonglong2 A23 = *reinterpret_cast<const ulonglong2*>(&a_s[buf][kk][mpb + 2]);
            accf[0] = fma2(A01.x, wf2, accf[0]);  acci[0] = fma2(A01.x, wi2, acci[0]);
            accf[1] = fma2(A01.y, wf2, accf[1]);  acci[1] = fma2(A01.y, wi2, acci[1]);
            accf[2] = fma2(A23.x, wf2, accf[2]);  acci[2] = fma2(A23.x, wi2, acci[2]);
            accf[3] = fma2(A23.y, wf2, accf[3]);  acci[3] = fma2(A23.y, wi2, acci[3]);
        }
    }

    // epilogue: gates + cell update (all table operands pre-loaded)
#pragma unroll
    for (int p = 0; p < 4; p++) {
        const int mp = (M0 >> 1) + mpb + p;       // global bpair
        float flo, fhi, ilo, ihi;
        upk2(accf[p], flo, fhi);
        upk2(acci[p], ilo, ihi);
        float c0o, c1o;
        upk2(hCold[p], c0o, c1o);
        const float f0 = sigmoidf_(flo + hGf[2 * p]);
        const float i0 = sigmoidf_(ilo + hGi[2 * p]);
        const float f1 = sigmoidf_(fhi + hGf[2 * p + 1]);
        const float i1 = sigmoidf_(ihi + hGi[2 * p + 1]);
        const float cn0 = hSc[2 * p]     * i0 + c0o * f0;
        const float cn1 = hSc[2 * p + 1] * i1 + c1o * f1;
        cout[(size_t)n * (BB/2) + mp] = pk2(cn0, cn1);
    }
}

// ---------------- kernel: final o-gate + hidden ----------------
// clast = g_c2[0] (written by t=511), cprev = g_c2[1] (written by t=510).
// h[b,n] = tanh(clast[b,n]) * sig(Go[cls,n] + cprev[b].Woh[n])
__global__ __launch_bounds__(256)
void final_o_kernel(const int* __restrict__ x) {
    const u64* __restrict__ cprev = g_c2[1];
    const u64* __restrict__ clast = g_c2[0];

    extern __shared__ __align__(16) char dynsm[];
    u64   (*a_s)[64][32]  = reinterpret_cast<u64(*)[64][32]>(dynsm);
    float (*wo_s)[64][32] = reinterpret_cast<float(*)[64][32]>(dynsm + 32768);
    __shared__ int cls_s[64];

    const int tid = threadIdx.x;
    const int M0  = blockIdx.y * 64;
    const int N0  = blockIdx.x * 32;
    if (tid < 64) cls_s[tid] = x[(M0 + tid) * SS + (SS - 1)];

    const int tx  = tid & 31;
    const int ty  = tid >> 5;
    const int mpb = ty * 4;

    const int arow  = tid >> 2;
    const int acolb = (tid & 3) * 8;
    const u64*   aS = cprev + (size_t)arow * (BB/2) + (M0 >> 1) + acolb;
    const float* oS = g_WoT + (size_t)arow * HH + N0 + acolb;

#pragma unroll
    for (int j = 0; j < 4; j++) cpa16(&a_s[0][arow][acolb + 2 * j], aS + 2 * j);
#pragma unroll
    for (int j = 0; j < 2; j++) cpa16(&wo_s[0][arow][acolb + 4 * j], oS + 4 * j);
    CP_COMMIT();

    u64 acco[4];
#pragma unroll
    for (int p = 0; p < 4; p++) acco[p] = 0ull;

#pragma unroll 1
    for (int it = 0; it < 16; it++) {
        const int buf = it & 1;
        CP_WAIT0();
        __syncthreads();
        if (it < 15) {
            const size_t aoff = (size_t)(it + 1) * 64 * (BB/2);
            const size_t woff = (size_t)(it + 1) * 64 * HH;
#pragma unroll
            for (int j = 0; j < 4; j++)
                cpa16(&a_s[buf ^ 1][arow][acolb + 2 * j], aS + aoff + 2 * j);
#pragma unroll
            for (int j = 0; j < 2; j++)
                cpa16(&wo_s[buf ^ 1][arow][acolb + 4 * j], oS + woff + 4 * j);
            CP_COMMIT();
        }
#pragma unroll
        for (int kk = 0; kk < 64; kk++) {
            const u64 wo2 = pk2b(wo_s[buf][kk][tx]);
            const ulonglong2 A01 = *reinterpret_cast<const ulonglong2*>(&a_s[buf][kk][mpb]);
            const ulonglong2 A23 = *reinterpret_cast<const ulonglong2*>(&a_s[buf][kk][mpb + 2]);
            acco[0] = fma2(A01.x, wo2, acco[0]);
            acco[1] = fma2(A01.y, wo2, acco[1]);
            acco[2] = fma2(A23.x, wo2, acco[2]);
            acco[3] = fma2(A23.y, wo2, acco[3]);
        }
    }

    const int n = N0 + tx;
#pragma unroll
    for (int p = 0; p < 4; p++) {
        const int mp = (M0 >> 1) + mpb + p;
        float olo, ohi;
        upk2(acco[p], olo, ohi);
        float cl0, cl1;
        upk2(clast[(size_t)n * (BB/2) + mp], cl0, cl1);
        const int lm   = 2 * (mpb + p);
        const int cls0 = cls_s[lm];
        const int cls1 = cls_s[lm + 1];
        const float o0 = sigmoidf_(olo + __ldg(&g_Go[cls0 * HH + n]));
        const float o1 = sigmoidf_(ohi + __ldg(&g_Go[cls1 * HH + n]));
        g_h[(size_t)(2 * mp)     * HH + n] = tanhf(cl0) * o0;
        g_h[(size_t)(2 * mp + 1) * HH + n] = tanhf(cl1) * o1;
    }
}

// ---------------- kernel: logits + log_softmax ----------------
__global__ __launch_bounds__(128)
void logits_kernel(const float* __restrict__ Wph, const float* __restrict__ bp,
                   float* __restrict__ out) {
    const int b = blockIdx.x;
    const int j = threadIdx.x;

    __shared__ __align__(16) float h_s[HH];
    __shared__ float red[128];

    const float4* hv  = reinterpret_cast<const float4*>(&g_h[(size_t)b * HH]);
    float4*       hs4 = reinterpret_cast<float4*>(h_s);
    for (int i = j; i < HH / 4; i += 128) hs4[i] = hv[i];
    __syncthreads();

    float acc = 0.f;
    const float4* w4 = reinterpret_cast<const float4*>(&Wph[(size_t)j * HH]);
#pragma unroll 4
    for (int k = 0; k < HH / 4; k++) {
        const float4 w = w4[k];
        const float4 h = hs4[k];
        acc = fmaf(h.x, w.x, acc);
        acc = fmaf(h.y, w.y, acc);
        acc = fmaf(h.z, w.z, acc);
        acc = fmaf(h.w, w.w, acc);
    }
    const float p = acc + bp[j];

    red[j] = p;
    __syncthreads();
    for (int s2 = 64; s2 > 0; s2 >>= 1) {
        if (j < s2) red[j] = fmaxf(red[j], red[j + s2]);
        __syncthreads();
    }
    const float mx = red[0];
    __syncthreads();
    red[j] = expf(p - mx);
    __syncthreads();
    for (int s2 = 64; s2 > 0; s2 >>= 1) {
        if (j < s2) red[j] += red[j + s2];
        __syncthreads();
    }
    const float lse = logf(red[0]) + mx;
    out[b * CC + j] = p - lse;
}

// ---------------- launcher ----------------
extern "C" void kernel_launch(void* const* d_in, const int* in_sizes, int n_in,
                              void* d_out, int out_size) {
    const int*   x   = (const int*)  d_in[0];
    const float* emb = (const float*)d_in[1];
    const float* Wcx = (const float*)d_in[2];
    const float* bc  = (const float*)d_in[3];
    const float* Wix = (const float*)d_in[4];
    const float* Wih = (const float*)d_in[5];
    const float* bi  = (const float*)d_in[6];
    const float* Wfx = (const float*)d_in[7];
    const float* Wfh = (const float*)d_in[8];
    const float* bf  = (const float*)d_in[9];
    const float* Wox = (const float*)d_in[10];
    const float* Woh = (const float*)d_in[11];
    const float* bo  = (const float*)d_in[12];
    const float* Wph = (const float*)d_in[13];
    const float* bp  = (const float*)d_in[14];
    float* out = (float*)d_out;

    float* wfT; cudaGetSymbolAddress((void**)&wfT, g_WfT);
    float* wiT; cudaGetSymbolAddress((void**)&wiT, g_WiT);
    float* woT; cudaGetSymbolAddress((void**)&woT, g_WoT);

    const int step_smem = 65536;                 // A 32K + Wf 16K + Wi 16K
    const int fino_smem = 49152;                 // A 32K + Wo 16K
    cudaFuncSetAttribute(step_kernel,
                         cudaFuncAttributeMaxDynamicSharedMemorySize, step_smem);
    cudaFuncSetAttribute(final_o_kernel,
                         cudaFuncAttributeMaxDynamicSharedMemorySize, fino_smem);

    transpose_kernel<<<dim3(32, 32), 256>>>(Wfh, wfT);
    transpose_kernel<<<dim3(32, 32), 256>>>(Wih, wiT);
    transpose_kernel<<<dim3(32, 32), 256>>>(Woh, woT);
    tab_kernel<<<dim3(32, 4), 256>>>(emb, Wfx, Wix, Wox, Wcx, bf, bi, bo, bc);

    const int zgrid = (C0_FLOAT4 + 255) / 256;   // exactly covers g_c2[0]
    zero_kernel<<<zgrid, 256>>>();

    for (int t = 0; t < SS; t++) {
        step_kernel<<<dim3(32, 4), 256, step_smem>>>(x, t);
    }

    final_o_kernel<<<dim3(32, 4), 256, fino_smem>>>(x);
    logits_kernel<<<BB, 128>>>(Wph, bp, out);
}

// round 9
// speedup vs baseline: 3.2176x; 1.9691x over previous
#include <cuda_runtime.h>
#include <cuda_bf16.h>
#include <math.h>

// Problem constants
#define BB 256   // batch
#define SS 512   // seq len
#define HH 1024  // hidden
#define EE 256   // input dim
#define CC 128   // num classes

typedef unsigned int u32;

// ---------------- device scratch ----------------
__device__ float g_Gf[CC * HH];              // emb@Wfx^T + bf
__device__ float g_Gi[CC * HH];              // emb@Wix^T + bi
__device__ float g_Go[CC * HH];              // emb@Wox^T + bo
__device__ float g_Sc[CC * HH];              // sigmoid(emb@Wcx^T + bc)
__device__ __nv_bfloat16 g_cst[2][2][BB * HH];   // cell state [buf][hi/lo][b*HH+k]
__device__ __nv_bfloat16 g_Wsp[6][HH * HH];      // split weights [fh,fl,ih,il,oh,ol][n*HH+k]
__device__ float g_h[BB * HH];               // final hidden [b][h]

// ---------------- helpers ----------------
__device__ __forceinline__ float sigmoidf_(float x) {
    return 1.0f / (1.0f + __expf(-x));
}
__device__ __forceinline__ u32 smem_u32(const void* p) {
    return (u32)__cvta_generic_to_shared(p);
}
__device__ __forceinline__ void cpa16(u32 dst, const void* src) {
    asm volatile("cp.async.cg.shared.global [%0], [%1], 16;\n" :: "r"(dst), "l"(src));
}
#define CP_COMMIT() asm volatile("cp.async.commit_group;\n" ::: "memory")
#define CP_WAIT0()  asm volatile("cp.async.wait_group 0;\n" ::: "memory")

__device__ __forceinline__ void ldsm4(u32& r0, u32& r1, u32& r2, u32& r3, u32 addr) {
    asm volatile("ldmatrix.sync.aligned.m8n8.x4.shared.b16 {%0,%1,%2,%3}, [%4];"
                 : "=r"(r0), "=r"(r1), "=r"(r2), "=r"(r3) : "r"(addr));
}
__device__ __forceinline__ void mma16816(float& d0, float& d1, float& d2, float& d3,
                                         u32 a0, u32 a1, u32 a2, u32 a3, u32 b0, u32 b1) {
    asm volatile("mma.sync.aligned.m16n8k16.row.col.f32.bf16.bf16.f32 "
                 "{%0,%1,%2,%3}, {%4,%5,%6,%7}, {%8,%9}, {%0,%1,%2,%3};"
                 : "+f"(d0), "+f"(d1), "+f"(d2), "+f"(d3)
                 : "r"(a0), "r"(a1), "r"(a2), "r"(a3), "r"(b0), "r"(b1));
}

// smem geometry (bytes). Rows padded 128B->144B for conflict-free LDSM.
#define ROWB     144
#define A_HI_OFF 0
#define A_LO_OFF 9216            // 64*144
#define W_OFF    18432
#define W_STRIDE 4608            // 32*144
#define BUF_STRIDE_S 36864       // step kernel: A(2) + W(4)
#define SMEM_STEP  (2 * BUF_STRIDE_S)       // 73728
#define BUF_STRIDE_F 27648       // final kernel: A(2) + W(2)
#define SMEM_FIN   (2 * BUF_STRIDE_F)       // 55296

// ---------------- kernel: zero initial cell state (exactly g_cst[0]) ----------------
#define CZ_FLOAT4 ((int)(sizeof(g_cst[0]) / sizeof(float4)))
__global__ void zero_kernel() {
    int i = blockIdx.x * blockDim.x + threadIdx.x;
    if (i < CZ_FLOAT4)
        reinterpret_cast<float4*>(g_cst[0])[i] = make_float4(0.f, 0.f, 0.f, 0.f);
}

// ---------------- kernel: split recurrent weights into bf16 hi/lo ----------------
__global__ __launch_bounds__(256)
void wsplit_kernel(const float* __restrict__ Wf, const float* __restrict__ Wi,
                   const float* __restrict__ Wo) {
    const int i = blockIdx.x * 256 + threadIdx.x;
    if (i >= HH * HH) return;
    {
        const float w = Wf[i];
        const __nv_bfloat16 h = __float2bfloat16(w);
        g_Wsp[0][i] = h;
        g_Wsp[1][i] = __float2bfloat16(w - __bfloat162float(h));
    }
    {
        const float w = Wi[i];
        const __nv_bfloat16 h = __float2bfloat16(w);
        g_Wsp[2][i] = h;
        g_Wsp[3][i] = __float2bfloat16(w - __bfloat162float(h));
    }
    {
        const float w = Wo[i];
        const __nv_bfloat16 h = __float2bfloat16(w);
        g_Wsp[4][i] = h;
        g_Wsp[5][i] = __float2bfloat16(w - __bfloat162float(h));
    }
}

// ---------------- kernel: precompute class->gate tables (unchanged) ----------------
__global__ __launch_bounds__(256)
void tab_kernel(const float* __restrict__ emb,
                const float* __restrict__ Wfx, const float* __restrict__ Wix,
                const float* __restrict__ Wox, const float* __restrict__ Wcx,
                const float* __restrict__ bf,  const float* __restrict__ bi,
                const float* __restrict__ bo,  const float* __restrict__ bc) {
    __shared__ float es[32][33];
    __shared__ float ws[4][32][33];

    const int tid = threadIdx.x;
    const int h0  = blockIdx.x * 32;
    const int c0b = blockIdx.y * 32;
    const int tx  = tid & 31;
    const int ty  = tid >> 5;

    float acc[4][4];
#pragma unroll
    for (int m = 0; m < 4; m++)
#pragma unroll
        for (int q = 0; q < 4; q++) acc[m][q] = 0.f;

    for (int k0 = 0; k0 < EE; k0 += 32) {
        __syncthreads();
        const int ccol  = tid & 31;
        const int rbase = tid >> 5;
#pragma unroll
        for (int rr = 0; rr < 4; rr++) {
            const int r = rbase + rr * 8;
            es[r][ccol]    = emb[(c0b + r) * EE + k0 + ccol];
            ws[0][r][ccol] = Wfx[(h0 + r) * EE + k0 + ccol];
            ws[1][r][ccol] = Wix[(h0 + r) * EE + k0 + ccol];
            ws[2][r][ccol] = Wox[(h0 + r) * EE + k0 + ccol];
            ws[3][r][ccol] = Wcx[(h0 + r) * EE + k0 + ccol];
        }
        __syncthreads();
#pragma unroll
        for (int kk = 0; kk < 32; kk++) {
            const float b0 = ws[0][tx][kk];
            const float b1 = ws[1][tx][kk];
            const float b2 = ws[2][tx][kk];
            const float b3 = ws[3][tx][kk];
#pragma unroll
            for (int q = 0; q < 4; q++) {
                const float a = es[ty + q * 8][kk];
                acc[0][q] = fmaf(a, b0, acc[0][q]);
                acc[1][q] = fmaf(a, b1, acc[1][q]);
                acc[2][q] = fmaf(a, b2, acc[2][q]);
                acc[3][q] = fmaf(a, b3, acc[3][q]);
            }
        }
    }

    const int h = h0 + tx;
    const float vbf = bf[h], vbi = bi[h], vbo = bo[h], vbc = bc[h];
#pragma unroll
    for (int q = 0; q < 4; q++) {
        const int cls = c0b + ty + q * 8;
        g_Gf[cls * HH + h] = acc[0][q] + vbf;
        g_Gi[cls * HH + h] = acc[1][q] + vbi;
        g_Go[cls * HH + h] = acc[2][q] + vbo;
        g_Sc[cls * HH + h] = sigmoidf_(acc[3][q] + vbc);
    }
}

// ---------------- kernel: one recurrence step (bf16-split tensor-core MMA) ----------------
// Tile M=64 (batch) x N=32 (hidden), BOTH gates. 8 warps: 4 along M x 2 along N,
// warp tile m16n16. K loop: 16 tiles of 64, 4 mma-k-chunks of 16 each,
// 3 split-products (AhBh + AhBl + AlBh) per gate.
__global__ __launch_bounds__(256)
void step_kernel(const int* __restrict__ x, int t) {
    const __nv_bfloat16* __restrict__ cih = g_cst[t & 1][0];
    const __nv_bfloat16* __restrict__ cil = g_cst[t & 1][1];
    __nv_bfloat16* __restrict__ coh = g_cst[(t & 1) ^ 1][0];
    __nv_bfloat16* __restrict__ clo = g_cst[(t & 1) ^ 1][1];

    extern __shared__ __align__(16) char dynsm[];
    __shared__ int cls_s[64];

    const int tid = threadIdx.x;
    const int M0  = blockIdx.y * 64;
    const int N0  = blockIdx.x * 32;
    if (tid < 64) cls_s[tid] = x[(M0 + tid) * SS + t];

    const int l   = tid & 31;
    const int wid = tid >> 5;
    const int wm  = wid >> 1;       // 0..3
    const int wn  = wid & 1;        // 0..1

    // ---- cp.async thread mapping ----
    // A: 64 rows x 8 16B-chunks, per half (hi/lo): 512 chunks -> 2/thread/half
    const int ar0 = tid >> 3;            // rows 0..31
    const int ar1 = (tid + 256) >> 3;    // rows 32..63
    const int ao  = tid & 7;
    const size_t sA0 = (size_t)(M0 + ar0) * HH + ao * 8;
    const size_t sA1 = (size_t)(M0 + ar1) * HH + ao * 8;
    const u32 dA0 = ar0 * ROWB + ao * 16;
    const u32 dA1 = ar1 * ROWB + ao * 16;
    // W: 32 rows x 8 chunks per array -> 1/thread/array
    const int wrow = tid >> 3;           // 0..31
    const size_t sW = (size_t)(N0 + wrow) * HH + ao * 8;
    const u32 dW = wrow * ROWB + ao * 16;

    const u32 sm0 = smem_u32(dynsm);

    // prefetch tile 0
    cpa16(sm0 + A_HI_OFF + dA0, cih + sA0);
    cpa16(sm0 + A_HI_OFF + dA1, cih + sA1);
    cpa16(sm0 + A_LO_OFF + dA0, cil + sA0);
    cpa16(sm0 + A_LO_OFF + dA1, cil + sA1);
#pragma unroll
    for (int arr = 0; arr < 4; arr++)
        cpa16(sm0 + W_OFF + arr * W_STRIDE + dW, g_Wsp[arr] + sW);
    CP_COMMIT();

    __syncthreads();   // cls_s visible

    // ---- hoisted epilogue operands ----
    const int qr = l >> 2;
    const int qc = (l & 3) * 2;
    float hGf[8], hGi[8], hSc[8], hCo[8];
#pragma unroll
    for (int p = 0; p < 8; p++) {
        const int j  = p >> 2;          // n-frag
        const int r  = (p >> 1) & 1;    // row half
        const int cc = p & 1;           // col within pair
        const int bl = wm * 16 + qr + r * 8;
        const int b  = M0 + bl;
        const int n  = N0 + wn * 16 + j * 8 + qc + cc;
        const int cls = cls_s[bl];
        hGf[p] = __ldg(&g_Gf[cls * HH + n]);
        hGi[p] = __ldg(&g_Gi[cls * HH + n]);
        hSc[p] = __ldg(&g_Sc[cls * HH + n]);
        hCo[p] = __bfloat162float(__ldg(&cih[(size_t)b * HH + n]))
               + __bfloat162float(__ldg(&cil[(size_t)b * HH + n]));
    }

    // ---- ldmatrix base addresses ----
    const u32 abase = sm0 + (wm * 16 + (l & 15)) * ROWB + ((l >> 4) & 1) * 16;
    const u32 wbase = sm0 + W_OFF
                    + ((l & 7) + ((l & 16) ? 8 : 0) + wn * 16) * ROWB
                    + ((l & 8) ? 16 : 0);

    float fa[8], ia[8];
#pragma unroll
    for (int p = 0; p < 8; p++) { fa[p] = 0.f; ia[p] = 0.f; }

#pragma unroll 1
    for (int it = 0; it < 16; it++) {
        const int buf = it & 1;
        CP_WAIT0();
        __syncthreads();
        if (it < 15) {
            const size_t kadv = (size_t)(it + 1) * 64;
            const u32 db = (buf ^ 1) * BUF_STRIDE_S;
            cpa16(sm0 + db + A_HI_OFF + dA0, cih + sA0 + kadv);
            cpa16(sm0 + db + A_HI_OFF + dA1, cih + sA1 + kadv);
            cpa16(sm0 + db + A_LO_OFF + dA0, cil + sA0 + kadv);
            cpa16(sm0 + db + A_LO_OFF + dA1, cil + sA1 + kadv);
#pragma unroll
            for (int arr = 0; arr < 4; arr++)
                cpa16(sm0 + db + W_OFF + arr * W_STRIDE + dW, g_Wsp[arr] + sW + kadv);
            CP_COMMIT();
        }

        const u32 ab = abase + buf * BUF_STRIDE_S;
        const u32 wb = wbase + buf * BUF_STRIDE_S;
#pragma unroll
        for (int kc = 0; kc < 4; kc++) {
            const u32 ko = kc * 32;
            u32 ah0, ah1, ah2, ah3, al0, al1, al2, al3;
            ldsm4(ah0, ah1, ah2, ah3, ab + ko);
            ldsm4(al0, al1, al2, al3, ab + A_LO_OFF + ko);
            u32 f0, f1, f2, f3, g0, g1, g2, g3;
            u32 h0, h1, h2, h3, j0, j1, j2, j3;
            ldsm4(f0, f1, f2, f3, wb + ko);                     // Wf hi
            ldsm4(g0, g1, g2, g3, wb + W_STRIDE + ko);          // Wf lo
            ldsm4(h0, h1, h2, h3, wb + 2 * W_STRIDE + ko);      // Wi hi
            ldsm4(j0, j1, j2, j3, wb + 3 * W_STRIDE + ko);      // Wi lo
            // f gate, n-frag 0 and 1
            mma16816(fa[0], fa[1], fa[2], fa[3], ah0, ah1, ah2, ah3, f0, f1);
            mma16816(fa[0], fa[1], fa[2], fa[3], ah0, ah1, ah2, ah3, g0, g1);
            mma16816(fa[0], fa[1], fa[2], fa[3], al0, al1, al2, al3, f0, f1);
            mma16816(fa[4], fa[5], fa[6], fa[7], ah0, ah1, ah2, ah3, f2, f3);
            mma16816(fa[4], fa[5], fa[6], fa[7], ah0, ah1, ah2, ah3, g2, g3);
            mma16816(fa[4], fa[5], fa[6], fa[7], al0, al1, al2, al3, f2, f3);
            // i gate
            mma16816(ia[0], ia[1], ia[2], ia[3], ah0, ah1, ah2, ah3, h0, h1);
            mma16816(ia[0], ia[1], ia[2], ia[3], ah0, ah1, ah2, ah3, j0, j1);
            mma16816(ia[0], ia[1], ia[2], ia[3], al0, al1, al2, al3, h0, h1);
            mma16816(ia[4], ia[5], ia[6], ia[7], ah0, ah1, ah2, ah3, h2, h3);
            mma16816(ia[4], ia[5], ia[6], ia[7], ah0, ah1, ah2, ah3, j2, j3);
            mma16816(ia[4], ia[5], ia[6], ia[7], al0, al1, al2, al3, h2, h3);
        }
    }

    // ---- epilogue: gates + cell update + re-split ----
#pragma unroll
    for (int p = 0; p < 8; p++) {
        const int j  = p >> 2;
        const int r  = (p >> 1) & 1;
        const int cc = p & 1;
        const int b  = M0 + wm * 16 + qr + r * 8;
        const int n  = N0 + wn * 16 + j * 8 + qc + cc;
        const int idx = j * 4 + r * 2 + cc;
        const float f  = sigmoidf_(fa[idx] + hGf[p]);
        const float ii = sigmoidf_(ia[idx] + hGi[p]);
        const float cn = hSc[p] * ii + hCo[p] * f;
        const __nv_bfloat16 hh = __float2bfloat16(cn);
        coh[(size_t)b * HH + n] = hh;
        clo[(size_t)b * HH + n] = __float2bfloat16(cn - __bfloat162float(hh));
    }
}

// ---------------- kernel: final o-gate + hidden (same MMA structure, 1 gate) ----------------
__global__ __launch_bounds__(256)
void final_o_kernel(const int* __restrict__ x) {
    const __nv_bfloat16* __restrict__ cih = g_cst[1][0];   // c_prev (written t=510)
    const __nv_bfloat16* __restrict__ cil = g_cst[1][1];
    const __nv_bfloat16* __restrict__ lih = g_cst[0][0];   // c_last (written t=511)
    const __nv_bfloat16* __restrict__ lil = g_cst[0][1];

    extern __shared__ __align__(16) char dynsm[];
    __shared__ int cls_s[64];

    const int tid = threadIdx.x;
    const int M0  = blockIdx.y * 64;
    const int N0  = blockIdx.x * 32;
    if (tid < 64) cls_s[tid] = x[(M0 + tid) * SS + (SS - 1)];

    const int l   = tid & 31;
    const int wid = tid >> 5;
    const int wm  = wid >> 1;
    const int wn  = wid & 1;

    const int ar0 = tid >> 3;
    const int ar1 = (tid + 256) >> 3;
    const int ao  = tid & 7;
    const size_t sA0 = (size_t)(M0 + ar0) * HH + ao * 8;
    const size_t sA1 = (size_t)(M0 + ar1) * HH + ao * 8;
    const u32 dA0 = ar0 * ROWB + ao * 16;
    const u32 dA1 = ar1 * ROWB + ao * 16;
    const int wrow = tid >> 3;
    const size_t sW = (size_t)(N0 + wrow) * HH + ao * 8;
    const u32 dW = wrow * ROWB + ao * 16;

    const u32 sm0 = smem_u32(dynsm);

    cpa16(sm0 + A_HI_OFF + dA0, cih + sA0);
    cpa16(sm0 + A_HI_OFF + dA1, cih + sA1);
    cpa16(sm0 + A_LO_OFF + dA0, cil + sA0);
    cpa16(sm0 + A_LO_OFF + dA1, cil + sA1);
    cpa16(sm0 + W_OFF + dW,            g_Wsp[4] + sW);
    cpa16(sm0 + W_OFF + W_STRIDE + dW, g_Wsp[5] + sW);
    CP_COMMIT();

    __syncthreads();

    const int qr = l >> 2;
    const int qc = (l & 3) * 2;
    float hGo[8], hCl[8];
#pragma unroll
    for (int p = 0; p < 8; p++) {
        const int j  = p >> 2;
        const int r  = (p >> 1) & 1;
        const int cc = p & 1;
        const int bl = wm * 16 + qr + r * 8;
        const int b  = M0 + bl;
        const int n  = N0 + wn * 16 + j * 8 + qc + cc;
        const int cls = cls_s[bl];
        hGo[p] = __ldg(&g_Go[cls * HH + n]);
        hCl[p] = __bfloat162float(__ldg(&lih[(size_t)b * HH + n]))
               + __bfloat162float(__ldg(&lil[(size_t)b * HH + n]));
    }

    const u32 abase = sm0 + (wm * 16 + (l & 15)) * ROWB + ((l >> 4) & 1) * 16;
    const u32 wbase = sm0 + W_OFF
                    + ((l & 7) + ((l & 16) ? 8 : 0) + wn * 16) * ROWB
                    + ((l & 8) ? 16 : 0);

    float oa[8];
#pragma unroll
    for (int p = 0; p < 8; p++) oa[p] = 0.f;

#pragma unroll 1
    for (int it = 0; it < 16; it++) {
        const int buf = it & 1;
        CP_WAIT0();
        __syncthreads();
        if (it < 15) {
            const size_t kadv = (size_t)(it + 1) * 64;
            const u32 db = (buf ^ 1) * BUF_STRIDE_F;
            cpa16(sm0 + db + A_HI_OFF + dA0, cih + sA0 + kadv);
            cpa16(sm0 + db + A_HI_OFF + dA1, cih + sA1 + kadv);
            cpa16(sm0 + db + A_LO_OFF + dA0, cil + sA0 + kadv);
            cpa16(sm0 + db + A_LO_OFF + dA1, cil + sA1 + kadv);
            cpa16(sm0 + db + W_OFF + dW,            g_Wsp[4] + sW + kadv);
            cpa16(sm0 + db + W_OFF + W_STRIDE + dW, g_Wsp[5] + sW + kadv);
            CP_COMMIT();
        }

        const u32 ab = abase + buf * BUF_STRIDE_F;
        const u32 wb = wbase + buf * BUF_STRIDE_F;
#pragma unroll
        for (int kc = 0; kc < 4; kc++) {
            const u32 ko = kc * 32;
            u32 ah0, ah1, ah2, ah3, al0, al1, al2, al3;
            ldsm4(ah0, ah1, ah2, ah3, ab + ko);
            ldsm4(al0, al1, al2, al3, ab + A_LO_OFF + ko);
            u32 o0, o1, o2, o3, q0, q1, q2, q3;
            ldsm4(o0, o1, o2, o3, wb + ko);                 // Wo hi
            ldsm4(q0, q1, q2, q3, wb + W_STRIDE + ko);      // Wo lo
            mma16816(oa[0], oa[1], oa[2], oa[3], ah0, ah1, ah2, ah3, o0, o1);
            mma16816(oa[0], oa[1], oa[2], oa[3], ah0, ah1, ah2, ah3, q0, q1);
            mma16816(oa[0], oa[1], oa[2], oa[3], al0, al1, al2, al3, o0, o1);
            mma16816(oa[4], oa[5], oa[6], oa[7], ah0, ah1, ah2, ah3, o2, o3);
            mma16816(oa[4], oa[5], oa[6], oa[7], ah0, ah1, ah2, ah3, q2, q3);
            mma16816(oa[4], oa[5], oa[6], oa[7], al0, al1, al2, al3, o2, o3);
        }
    }

#pragma unroll
    for (int p = 0; p < 8; p++) {
        const int j  = p >> 2;
        const int r  = (p >> 1) & 1;
        const int cc = p & 1;
        const int b  = M0 + wm * 16 + qr + r * 8;
        const int n  = N0 + wn * 16 + j * 8 + qc + cc;
        const int idx = j * 4 + r * 2 + cc;
        const float o = sigmoidf_(oa[idx] + hGo[p]);
        g_h[(size_t)b * HH + n] = tanhf(hCl[p]) * o;
    }
}

// ---------------- kernel: logits + log_softmax ----------------
__global__ __launch_bounds__(128)
void logits_kernel(const float* __restrict__ Wph, const float* __restrict__ bp,
                   float* __restrict__ out) {
    const int b = blockIdx.x;
    const int j = threadIdx.x;

    __shared__ __align__(16) float h_s[HH];
    __shared__ float red[128];

    const float4* hv  = reinterpret_cast<const float4*>(&g_h[(size_t)b * HH]);
    float4*       hs4 = reinterpret_cast<float4*>(h_s);
    for (int i = j; i < HH / 4; i += 128) hs4[i] = hv[i];
    __syncthreads();

    float acc = 0.f;
    const float4* w4 = reinterpret_cast<const float4*>(&Wph[(size_t)j * HH]);
#pragma unroll 4
    for (int k = 0; k < HH / 4; k++) {
        const float4 w = w4[k];
        const float4 h = hs4[k];
        acc = fmaf(h.x, w.x, acc);
        acc = fmaf(h.y, w.y, acc);
        acc = fmaf(h.z, w.z, acc);
        acc = fmaf(h.w, w.w, acc);
    }
    const float p = acc + bp[j];

    red[j] = p;
    __syncthreads();
    for (int s2 = 64; s2 > 0; s2 >>= 1) {
        if (j < s2) red[j] = fmaxf(red[j], red[j + s2]);
        __syncthreads();
    }
    const float mx = red[0];
    __syncthreads();
    red[j] = expf(p - mx);
    __syncthreads();
    for (int s2 = 64; s2 > 0; s2 >>= 1) {
        if (j < s2) red[j] += red[j + s2];
        __syncthreads();
    }
    const float lse = logf(red[0]) + mx;
    out[b * CC + j] = p - lse;
}

// ---------------- launcher ----------------
extern "C" void kernel_launch(void* const* d_in, const int* in_sizes, int n_in,
                              void* d_out, int out_size) {
    const int*   x   = (const int*)  d_in[0];
    const float* emb = (const float*)d_in[1];
    const float* Wcx = (const float*)d_in[2];
    const float* bc  = (const float*)d_in[3];
    const float* Wix = (const float*)d_in[4];
    const float* Wih = (const float*)d_in[5];
    const float* bi  = (const float*)d_in[6];
    const float* Wfx = (const float*)d_in[7];
    const float* Wfh = (const float*)d_in[8];
    const float* bf  = (const float*)d_in[9];
    const float* Wox = (const float*)d_in[10];
    const float* Woh = (const float*)d_in[11];
    const float* bo  = (const float*)d_in[12];
    const float* Wph = (const float*)d_in[13];
    const float* bp  = (const float*)d_in[14];
    float* out = (float*)d_out;

    cudaFuncSetAttribute(step_kernel,
                         cudaFuncAttributeMaxDynamicSharedMemorySize, SMEM_STEP);
    cudaFuncSetAttribute(final_o_kernel,
                         cudaFuncAttributeMaxDynamicSharedMemorySize, SMEM_FIN);

    wsplit_kernel<<<(HH * HH + 255) / 256, 256>>>(Wfh, Wih, Woh);
    tab_kernel<<<dim3(32, 4), 256>>>(emb, Wfx, Wix, Wox, Wcx, bf, bi, bo, bc);

    const int zgrid = (CZ_FLOAT4 + 255) / 256;
    zero_kernel<<<zgrid, 256>>>();

    for (int t = 0; t < SS; t++) {
        step_kernel<<<dim3(32, 4), 256, SMEM_STEP>>>(x, t);
    }

    final_o_kernel<<<dim3(32, 4), 256, SMEM_FIN>>>(x);
    logits_kernel<<<BB, 128>>>(Wph, bp, out);
}